// round 2
// baseline (speedup 1.0000x reference)
#include <cuda_runtime.h>
#include <mma.h>

using namespace nvcuda;

// Problem constants
#define IN_DIM 512
#define BATCH  1024
#define NN1    25
#define NN2    10
#define D1     128
#define D2     128
#define NCLS   41
#define ROWS1  (BATCH * NN1)        // 25600

// Scratch (device globals; no cudaMalloc allowed)
__device__ float g_agg2[ROWS1 * IN_DIM];   // 52.4 MB
__device__ float g_h2  [ROWS1 * 2 * D2];   // 26.2 MB (raw GEMM out, pre-bias/relu)
__device__ float g_agg1[BATCH * 2 * D2];   // 1 MB

// ---------------------------------------------------------------------------
// Kernel A: agg2[i,d] = mean_k flat[i*5120 + d*10 + k], flat = gathered f2 rows
// One block per group of 10 rows. 128 threads.
// ---------------------------------------------------------------------------
__global__ void agg2_kernel(const float* __restrict__ features,
                            const int* __restrict__ ids2) {
    __shared__ float sbuf[NN2 * IN_DIM];   // 5120 floats
    __shared__ int   sIds[NN2];
    const int g   = blockIdx.x;
    const int tid = threadIdx.x;

    if (tid < NN2) sIds[tid] = ids2[g * NN2 + tid];
    __syncthreads();

    // Coalesced gather of 10 rows (float4)
    float4* s4 = reinterpret_cast<float4*>(sbuf);
    for (int i = tid; i < NN2 * IN_DIM / 4; i += 128) {
        const int r  = i >> 7;    // /128 float4 per row
        const int c4 = i & 127;
        const float4* src = reinterpret_cast<const float4*>(
            features + (size_t)sIds[r] * IN_DIM) + c4;
        s4[i] = *src;
    }
    __syncthreads();

    float* outRow = g_agg2 + (size_t)g * IN_DIM;
#pragma unroll
    for (int j = 0; j < 4; j++) {
        const int d = tid + j * 128;
        const float* p = sbuf + d * NN2;
        float s = 0.f;
#pragma unroll
        for (int k = 0; k < NN2; k++) s += p[k];
        outRow[d] = s * (1.0f / NN2);
    }
}

// ---------------------------------------------------------------------------
// Kernel B: h2_raw = A @ W  (no bias/relu; folded into agg1)
//   half 0: A = features[ids1[r]],  W = W2s  -> h2[:, 0:128]
//   half 1: A = g_agg2[r],          W = W2n  -> h2[:, 128:256]
// wmma tf32 16x16x8, fp32 accumulate. BM=64, BN=128, BK=32, 256 threads.
// ---------------------------------------------------------------------------
#define BM  64
#define BK  32
#define LDA 36
#define LDB 132

__global__ void gemm2_kernel(const float* __restrict__ features,
                             const int* __restrict__ ids1,
                             const float* __restrict__ W2s,
                             const float* __restrict__ W2n) {
    __shared__ float sA[BM * LDA];   // 2304 floats
    __shared__ float sB[BK * LDB];   // 4224 floats
    __shared__ int   sIds[BM];

    const int half = blockIdx.y;
    const int tid  = threadIdx.x;
    const int row0 = blockIdx.x * BM;
    const float* __restrict__ W = half ? W2n : W2s;

    if (half == 0 && tid < BM) sIds[tid] = ids1[row0 + tid];
    __syncthreads();

    wmma::fragment<wmma::accumulator, 16, 16, 8, float> acc[2][2];
#pragma unroll
    for (int i = 0; i < 2; i++)
#pragma unroll
        for (int j = 0; j < 2; j++) wmma::fill_fragment(acc[i][j], 0.0f);

    const int warp = tid >> 5;
    const int m0 = (warp >> 2) * 32;   // 0 or 32
    const int n0 = (warp & 3) * 32;    // 0,32,64,96

    for (int kt = 0; kt < IN_DIM / BK; kt++) {
        // Load A tile (64 x 32): 512 float4
        for (int i = tid; i < BM * BK / 4; i += 256) {
            const int r  = i >> 3;
            const int c4 = i & 7;
            const float* src = (half == 0)
                ? features + (size_t)sIds[r] * IN_DIM + kt * BK + c4 * 4
                : g_agg2  + (size_t)(row0 + r) * IN_DIM + kt * BK + c4 * 4;
            *reinterpret_cast<float4*>(&sA[r * LDA + c4 * 4]) =
                *reinterpret_cast<const float4*>(src);
        }
        // Load B tile (32 x 128): 1024 float4
        for (int i = tid; i < BK * 128 / 4; i += 256) {
            const int r  = i >> 5;
            const int c4 = i & 31;
            *reinterpret_cast<float4*>(&sB[r * LDB + c4 * 4]) =
                *reinterpret_cast<const float4*>(
                    W + (size_t)(kt * BK + r) * 128 + c4 * 4);
        }
        __syncthreads();

#pragma unroll
        for (int kk = 0; kk < BK; kk += 8) {
            wmma::fragment<wmma::matrix_a, 16, 16, 8, wmma::precision::tf32,
                           wmma::row_major> af[2];
            wmma::fragment<wmma::matrix_b, 16, 16, 8, wmma::precision::tf32,
                           wmma::row_major> bf[2];
#pragma unroll
            for (int i = 0; i < 2; i++) {
                wmma::load_matrix_sync(af[i], &sA[(m0 + i * 16) * LDA + kk], LDA);
#pragma unroll
                for (int t = 0; t < af[i].num_elements; t++)
                    af[i].x[t] = wmma::__float_to_tf32(af[i].x[t]);
            }
#pragma unroll
            for (int j = 0; j < 2; j++) {
                wmma::load_matrix_sync(bf[j], &sB[kk * LDB + n0 + j * 16], LDB);
#pragma unroll
                for (int t = 0; t < bf[j].num_elements; t++)
                    bf[j].x[t] = wmma::__float_to_tf32(bf[j].x[t]);
            }
#pragma unroll
            for (int i = 0; i < 2; i++)
#pragma unroll
                for (int j = 0; j < 2; j++)
                    wmma::mma_sync(acc[i][j], af[i], bf[j], acc[i][j]);
        }
        __syncthreads();
    }

#pragma unroll
    for (int i = 0; i < 2; i++)
#pragma unroll
        for (int j = 0; j < 2; j++)
            wmma::store_matrix_sync(
                g_h2 + (size_t)(row0 + m0 + i * 16) * (2 * D2) + half * D2 + n0 + j * 16,
                acc[i][j], 2 * D2, wmma::mem_row_major);
}

// ---------------------------------------------------------------------------
// Kernel C: agg1[b,d] = mean_k relu(h2_raw + bias)[flat b*6400 + d*25 + k]
// bias[c] = c<128 ? b2s[c] : b2n[c-128]. One block per batch element, 256 thr.
// ---------------------------------------------------------------------------
__global__ void agg1_kernel(const float* __restrict__ b2s,
                            const float* __restrict__ b2n) {
    __shared__ float sbuf[NN1 * 2 * D2];   // 6400 floats
    __shared__ float sbias[2 * D2];
    const int g   = blockIdx.x;
    const int tid = threadIdx.x;   // 256

    sbias[tid] = (tid < D2) ? b2s[tid] : b2n[tid - D2];
    __syncthreads();

    const float* src = g_h2 + (size_t)g * NN1 * 2 * D2;
    for (int i = tid; i < NN1 * 2 * D2; i += 256) {
        const int c = i & 255;
        sbuf[i] = fmaxf(src[i] + sbias[c], 0.0f);
    }
    __syncthreads();

    const float* p = sbuf + tid * NN1;
    float s = 0.f;
#pragma unroll
    for (int k = 0; k < NN1; k++) s += p[k];
    g_agg1[g * 2 * D2 + tid] = s * (1.0f / NN1);
}

// ---------------------------------------------------------------------------
// Kernel D: h1 = [f0@W1s+b1s, agg1@W1n+b1n]; out = h1@Wfc + bfc
// 8 rows per block (weight reuse), 128 threads.
// ---------------------------------------------------------------------------
#define RPB 8
__global__ void head_kernel(const float* __restrict__ features,
                            const int* __restrict__ ids0,
                            const float* __restrict__ W1s,
                            const float* __restrict__ b1s,
                            const float* __restrict__ W1n,
                            const float* __restrict__ b1n,
                            const float* __restrict__ Wfc,
                            const float* __restrict__ bfc,
                            float* __restrict__ out) {
    __shared__ float sF0[RPB * IN_DIM];     // 16 KB
    __shared__ float sA1[RPB * 2 * D2];     // 8 KB
    __shared__ float sH1[RPB * 2 * D1];     // 8 KB
    const int blk = blockIdx.x;
    const int tid = threadIdx.x;   // 128

    for (int i = tid; i < RPB * IN_DIM / 4; i += 128) {
        const int r  = i >> 7;
        const int c4 = i & 127;
        const int id = ids0[blk * RPB + r];
        reinterpret_cast<float4*>(sF0)[i] =
            *(reinterpret_cast<const float4*>(features + (size_t)id * IN_DIM) + c4);
    }
    for (int i = tid; i < RPB * 2 * D2 / 4; i += 128) {
        reinterpret_cast<float4*>(sA1)[i] =
            reinterpret_cast<const float4*>(g_agg1 + (size_t)blk * RPB * 2 * D2)[i];
    }
    __syncthreads();

    float acc[RPB];
#pragma unroll
    for (int r = 0; r < RPB; r++) acc[r] = 0.f;
    for (int k = 0; k < IN_DIM; k++) {
        const float w = W1s[k * D1 + tid];
#pragma unroll
        for (int r = 0; r < RPB; r++) acc[r] = fmaf(sF0[r * IN_DIM + k], w, acc[r]);
    }
    {
        const float bb = b1s[tid];
#pragma unroll
        for (int r = 0; r < RPB; r++) sH1[r * 2 * D1 + tid] = acc[r] + bb;
    }
#pragma unroll
    for (int r = 0; r < RPB; r++) acc[r] = 0.f;
    for (int k = 0; k < 2 * D2; k++) {
        const float w = W1n[k * D1 + tid];
#pragma unroll
        for (int r = 0; r < RPB; r++) acc[r] = fmaf(sA1[r * 2 * D2 + k], w, acc[r]);
    }
    {
        const float bb = b1n[tid];
#pragma unroll
        for (int r = 0; r < RPB; r++) sH1[r * 2 * D1 + D1 + tid] = acc[r] + bb;
    }
    __syncthreads();

    for (int o = tid; o < RPB * NCLS; o += 128) {
        const int r = o / NCLS;
        const int c = o % NCLS;
        float s = bfc[c];
        const float* h = sH1 + r * 2 * D1;
        for (int k = 0; k < 2 * D1; k++) s = fmaf(h[k], Wfc[k * NCLS + c], s);
        out[(blk * RPB + r) * NCLS + c] = s;
    }
}

// ---------------------------------------------------------------------------
extern "C" void kernel_launch(void* const* d_in, const int* in_sizes, int n_in,
                              void* d_out, int out_size) {
    const float* features = (const float*)d_in[0];
    const int*   ids0     = (const int*)  d_in[1];
    const int*   ids1     = (const int*)  d_in[2];
    const int*   ids2     = (const int*)  d_in[3];
    const float* W2s      = (const float*)d_in[4];
    const float* b2s      = (const float*)d_in[5];
    const float* W2n      = (const float*)d_in[6];
    const float* b2n      = (const float*)d_in[7];
    const float* W1s      = (const float*)d_in[8];
    const float* b1s      = (const float*)d_in[9];
    const float* W1n      = (const float*)d_in[10];
    const float* b1n      = (const float*)d_in[11];
    const float* Wfc      = (const float*)d_in[12];
    const float* bfc      = (const float*)d_in[13];
    float* out = (float*)d_out;

    agg2_kernel<<<ROWS1, 128>>>(features, ids2);
    gemm2_kernel<<<dim3(ROWS1 / BM, 2), 256>>>(features, ids1, W2s, W2n);
    agg1_kernel<<<BATCH, 256>>>(b2s, b2n);
    head_kernel<<<BATCH / RPB, 128>>>(features, ids0, W1s, b1s, W1n, b1n,
                                      Wfc, bfc, out);
}

// round 3
// speedup vs baseline: 1.3834x; 1.3834x over previous
#include <cuda_runtime.h>
#include <mma.h>

using namespace nvcuda;

// Problem constants
#define IN_DIM 512
#define BATCH  1024
#define NN1    25
#define NN2    10
#define D1     128
#define D2     128
#define NCLS   41
#define ROWS1  (BATCH * NN1)        // 25600

// Scratch (device globals; no cudaMalloc allowed)
__device__ float g_agg2[ROWS1 * IN_DIM];   // 52.4 MB
__device__ float g_h2  [ROWS1 * 2 * D2];   // 26.2 MB (raw GEMM out, pre-bias/relu)
__device__ float g_agg1[BATCH * 2 * D2];   // 1 MB

// ---------------------------------------------------------------------------
// Kernel A: agg2[i,d] = mean_k flat[i*5120 + d*10 + k], flat = gathered f2 rows
// One block per group of 10 rows. 128 threads.
// ---------------------------------------------------------------------------
__global__ void agg2_kernel(const float* __restrict__ features,
                            const int* __restrict__ ids2) {
    __shared__ float sbuf[NN2 * IN_DIM];   // 5120 floats
    __shared__ int   sIds[NN2];
    const int g   = blockIdx.x;
    const int tid = threadIdx.x;

    if (tid < NN2) sIds[tid] = ids2[g * NN2 + tid];
    __syncthreads();

    // Coalesced gather of 10 rows (float4)
    float4* s4 = reinterpret_cast<float4*>(sbuf);
    for (int i = tid; i < NN2 * IN_DIM / 4; i += 128) {
        const int r  = i >> 7;    // /128 float4 per row
        const int c4 = i & 127;
        const float4* src = reinterpret_cast<const float4*>(
            features + (size_t)sIds[r] * IN_DIM) + c4;
        s4[i] = *src;
    }
    __syncthreads();

    float* outRow = g_agg2 + (size_t)g * IN_DIM;
#pragma unroll
    for (int j = 0; j < 4; j++) {
        const int d = tid + j * 128;
        const float* p = sbuf + d * NN2;
        float s = 0.f;
#pragma unroll
        for (int k = 0; k < NN2; k++) s += p[k];
        outRow[d] = s * (1.0f / NN2);
    }
}

// ---------------------------------------------------------------------------
// Kernel B: h2_raw = A @ W  (no bias/relu; folded into agg1)
//   half 0: A = features[ids1[r]],  W = W2s  -> h2[:, 0:128]
//   half 1: A = g_agg2[r],          W = W2n  -> h2[:, 128:256]
// wmma tf32 16x16x8, fp32 accumulate. BM=64, BN=128, BK=32, 256 threads.
// ---------------------------------------------------------------------------
#define BM  64
#define BK  32
#define LDA 36
#define LDB 132

__global__ void gemm2_kernel(const float* __restrict__ features,
                             const int* __restrict__ ids1,
                             const float* __restrict__ W2s,
                             const float* __restrict__ W2n) {
    __shared__ float sA[BM * LDA];   // 2304 floats
    __shared__ float sB[BK * LDB];   // 4224 floats
    __shared__ int   sIds[BM];

    const int half = blockIdx.y;
    const int tid  = threadIdx.x;
    const int row0 = blockIdx.x * BM;
    const float* __restrict__ W = half ? W2n : W2s;

    if (half == 0 && tid < BM) sIds[tid] = ids1[row0 + tid];
    __syncthreads();

    wmma::fragment<wmma::accumulator, 16, 16, 8, float> acc[2][2];
#pragma unroll
    for (int i = 0; i < 2; i++)
#pragma unroll
        for (int j = 0; j < 2; j++) wmma::fill_fragment(acc[i][j], 0.0f);

    const int warp = tid >> 5;
    const int m0 = (warp >> 2) * 32;   // 0 or 32
    const int n0 = (warp & 3) * 32;    // 0,32,64,96

    for (int kt = 0; kt < IN_DIM / BK; kt++) {
        // Load A tile (64 x 32): 512 float4
        for (int i = tid; i < BM * BK / 4; i += 256) {
            const int r  = i >> 3;
            const int c4 = i & 7;
            const float* src = (half == 0)
                ? features + (size_t)sIds[r] * IN_DIM + kt * BK + c4 * 4
                : g_agg2  + (size_t)(row0 + r) * IN_DIM + kt * BK + c4 * 4;
            *reinterpret_cast<float4*>(&sA[r * LDA + c4 * 4]) =
                *reinterpret_cast<const float4*>(src);
        }
        // Load B tile (32 x 128): 1024 float4
        for (int i = tid; i < BK * 128 / 4; i += 256) {
            const int r  = i >> 5;
            const int c4 = i & 31;
            *reinterpret_cast<float4*>(&sB[r * LDB + c4 * 4]) =
                *reinterpret_cast<const float4*>(
                    W + (size_t)(kt * BK + r) * 128 + c4 * 4);
        }
        __syncthreads();

#pragma unroll
        for (int kk = 0; kk < BK; kk += 8) {
            wmma::fragment<wmma::matrix_a, 16, 16, 8, wmma::precision::tf32,
                           wmma::row_major> af[2];
            wmma::fragment<wmma::matrix_b, 16, 16, 8, wmma::precision::tf32,
                           wmma::row_major> bf[2];
#pragma unroll
            for (int i = 0; i < 2; i++) {
                wmma::load_matrix_sync(af[i], &sA[(m0 + i * 16) * LDA + kk], LDA);
#pragma unroll
                for (int t = 0; t < af[i].num_elements; t++)
                    af[i].x[t] = wmma::__float_to_tf32(af[i].x[t]);
            }
#pragma unroll
            for (int j = 0; j < 2; j++) {
                wmma::load_matrix_sync(bf[j], &sB[kk * LDB + n0 + j * 16], LDB);
#pragma unroll
                for (int t = 0; t < bf[j].num_elements; t++)
                    bf[j].x[t] = wmma::__float_to_tf32(bf[j].x[t]);
            }
#pragma unroll
            for (int i = 0; i < 2; i++)
#pragma unroll
                for (int j = 0; j < 2; j++)
                    wmma::mma_sync(acc[i][j], af[i], bf[j], acc[i][j]);
        }
        __syncthreads();
    }

#pragma unroll
    for (int i = 0; i < 2; i++)
#pragma unroll
        for (int j = 0; j < 2; j++)
            wmma::store_matrix_sync(
                g_h2 + (size_t)(row0 + m0 + i * 16) * (2 * D2) + half * D2 + n0 + j * 16,
                acc[i][j], 2 * D2, wmma::mem_row_major);
}

// ---------------------------------------------------------------------------
// Kernel C: agg1[b,d] = mean_k relu(h2_raw + bias)[flat b*6400 + d*25 + k]
// bias[c] = c<128 ? b2s[c] : b2n[c-128]. One block per batch element, 256 thr.
// ---------------------------------------------------------------------------
__global__ void agg1_kernel(const float* __restrict__ b2s,
                            const float* __restrict__ b2n) {
    __shared__ float sbuf[NN1 * 2 * D2];   // 6400 floats
    __shared__ float sbias[2 * D2];
    const int g   = blockIdx.x;
    const int tid = threadIdx.x;   // 256

    sbias[tid] = (tid < D2) ? b2s[tid] : b2n[tid - D2];
    __syncthreads();

    const float* src = g_h2 + (size_t)g * NN1 * 2 * D2;
    for (int i = tid; i < NN1 * 2 * D2; i += 256) {
        const int c = i & 255;
        sbuf[i] = fmaxf(src[i] + sbias[c], 0.0f);
    }
    __syncthreads();

    const float* p = sbuf + tid * NN1;
    float s = 0.f;
#pragma unroll
    for (int k = 0; k < NN1; k++) s += p[k];
    g_agg1[g * 2 * D2 + tid] = s * (1.0f / NN1);
}

// ---------------------------------------------------------------------------
// Kernel D (rewritten): one block per batch row, 256 threads.
//   h1[row] = [f0@W1s+b1s, agg1@W1n+b1n]  (256 cols, one thread per col,
//             4 interleaved accumulators to break the FMA RAW chain)
//   out[row] = h1@Wfc + bfc               (warp-parallel dots + shfl reduce)
// Weights stay L2-resident, reused across all 1024 blocks.
// ---------------------------------------------------------------------------
__global__ void head_kernel(const float* __restrict__ features,
                            const int* __restrict__ ids0,
                            const float* __restrict__ W1s,
                            const float* __restrict__ b1s,
                            const float* __restrict__ W1n,
                            const float* __restrict__ b1n,
                            const float* __restrict__ Wfc,
                            const float* __restrict__ bfc,
                            float* __restrict__ out) {
    __shared__ float sF0[IN_DIM];      // 512 floats
    __shared__ float sA1[2 * D2];      // 256 floats
    __shared__ float sH1[2 * D1];      // 256 floats
    const int row = blockIdx.x;
    const int tid = threadIdx.x;       // 256

    // Gather f0 row (128 float4) + agg1 row (64 float4)
    {
        const int id = ids0[row];
        const float4* f4 = reinterpret_cast<const float4*>(
            features + (size_t)id * IN_DIM);
        if (tid < 128) reinterpret_cast<float4*>(sF0)[tid] = f4[tid];
        else {
            const int j = tid - 128;
            if (j < 64)
                reinterpret_cast<float4*>(sA1)[j] =
                    reinterpret_cast<const float4*>(g_agg1 + row * 2 * D2)[j];
        }
    }
    __syncthreads();

    // h1: thread tid<128 -> self path (K=512); tid>=128 -> neigh path (K=256)
    if (tid < D1) {
        float a0 = 0.f, a1 = 0.f, a2 = 0.f, a3 = 0.f;
#pragma unroll 8
        for (int k = 0; k < IN_DIM; k += 4) {
            a0 = fmaf(sF0[k + 0], W1s[(k + 0) * D1 + tid], a0);
            a1 = fmaf(sF0[k + 1], W1s[(k + 1) * D1 + tid], a1);
            a2 = fmaf(sF0[k + 2], W1s[(k + 2) * D1 + tid], a2);
            a3 = fmaf(sF0[k + 3], W1s[(k + 3) * D1 + tid], a3);
        }
        sH1[tid] = (a0 + a1) + (a2 + a3) + b1s[tid];
    } else {
        const int t = tid - D1;
        float a0 = 0.f, a1 = 0.f, a2 = 0.f, a3 = 0.f;
#pragma unroll 8
        for (int k = 0; k < 2 * D2; k += 4) {
            a0 = fmaf(sA1[k + 0], W1n[(k + 0) * D1 + t], a0);
            a1 = fmaf(sA1[k + 1], W1n[(k + 1) * D1 + t], a1);
            a2 = fmaf(sA1[k + 2], W1n[(k + 2) * D1 + t], a2);
            a3 = fmaf(sA1[k + 3], W1n[(k + 3) * D1 + t], a3);
        }
        sH1[D1 + t] = (a0 + a1) + (a2 + a3) + b1n[t];
    }
    __syncthreads();

    // Classifier: 8 warps, classes strided by warp; lanes split K, shfl reduce
    const int warp = tid >> 5;
    const int lane = tid & 31;
    for (int c = warp; c < NCLS; c += 8) {
        float s = 0.f;
#pragma unroll
        for (int k = lane; k < 2 * D1; k += 32)
            s = fmaf(sH1[k], Wfc[k * NCLS + c], s);
#pragma unroll
        for (int off = 16; off > 0; off >>= 1)
            s += __shfl_xor_sync(0xFFFFFFFFu, s, off);
        if (lane == 0) out[row * NCLS + c] = s + bfc[c];
    }
}

// ---------------------------------------------------------------------------
extern "C" void kernel_launch(void* const* d_in, const int* in_sizes, int n_in,
                              void* d_out, int out_size) {
    const float* features = (const float*)d_in[0];
    const int*   ids0     = (const int*)  d_in[1];
    const int*   ids1     = (const int*)  d_in[2];
    const int*   ids2     = (const int*)  d_in[3];
    const float* W2s      = (const float*)d_in[4];
    const float* b2s      = (const float*)d_in[5];
    const float* W2n      = (const float*)d_in[6];
    const float* b2n      = (const float*)d_in[7];
    const float* W1s      = (const float*)d_in[8];
    const float* b1s      = (const float*)d_in[9];
    const float* W1n      = (const float*)d_in[10];
    const float* b1n      = (const float*)d_in[11];
    const float* Wfc      = (const float*)d_in[12];
    const float* bfc      = (const float*)d_in[13];
    float* out = (float*)d_out;

    agg2_kernel<<<ROWS1, 128>>>(features, ids2);
    gemm2_kernel<<<dim3(ROWS1 / BM, 2), 256>>>(features, ids1, W2s, W2n);
    agg1_kernel<<<BATCH, 256>>>(b2s, b2n);
    head_kernel<<<BATCH, 256>>>(features, ids0, W1s, b1s, W1n, b1n,
                                Wfc, bfc, out);
}